// round 13
// baseline (speedup 1.0000x reference)
#include <cuda_runtime.h>

// ---------------- problem constants ----------------
#define NPTS   32768        // B*P
#define PP     1024         // points per sample
#define NB     32           // batch
#define FF     64           // feature dim
#define KK     32           // max neighbors
#define C1     128          // hidden dim
#define NSLOT  1024         // stat partial slots (one per stats block)
#define ENC_NEG_INF 0x007FFFFFu
#define CAP    128          // candidate cap in k_nbr
#define GC     8            // spatial grid cells per dim (cell 0.125 > R 0.1)

#define HSH 72              // hs stride: 64 slots + 8 pad
#define WS  136             // W2t smem stride: 128 slots + 8 pad
#define SMEM_MAIN_FLOATS (128*HSH + 64*WS + 128 + 128 + 128 + 256)
#define SMEM_MAIN_BYTES  (SMEM_MAIN_FLOATS * 4)

#define NBR_BLOCKS  (NPTS / 4)     // 8192 neighbor-mode blocks
#define SELF_BLOCKS (NPTS / 128)   // 256 self-mode blocks

// ---------------- device scratch (static, no allocation) ----------------
// hidden dim stored in PERMUTED "slot" space: slot j = 2t + hi <-> channel t + 4*hi
__device__ float    g_Y[NPTS * C1];         // x @ W1[:64], slot cols (16 MB)
__device__ int      g_pix[NPTS];
__device__ int      g_nbr[NPTS * KK];
__device__ float    g_psum[NSLOT * C1];
__device__ float    g_psq [NSLOT * C1];
__device__ int      g_pcnt[NSLOT];
__device__ float    g_coef[4 * C1];         // alpha | w64*a | w65*a | beta+(b1-mean)*a (slot space)
__device__ float    g_W2t[64 * C1];         // W2 transposed [n][slot], tf32 bits
__device__ int      g_cnt;                  // last-block-reduce counter

__device__ __forceinline__ int ch_of_slot(int s) {
    int j = s & 7;
    return (s & ~7) | ((j >> 1) + ((j & 1) << 2));
}

__device__ __forceinline__ unsigned encf(float f) {
    unsigned u = __float_as_uint(f);
    return (u & 0x80000000u) ? ~u : (u | 0x80000000u);
}
__device__ __forceinline__ float decf(unsigned u) {
    return (u & 0x80000000u) ? __uint_as_float(u & 0x7fffffffu)
                             : __uint_as_float(~u);
}
__device__ __forceinline__ unsigned f2tf32(float f) {
    unsigned u;
    asm("cvt.rna.tf32.f32 %0, %1;" : "=r"(u) : "f"(f));
    return u;
}

// depth-5 tree argmax over best[32]
__device__ __forceinline__ void tree_max32(const float* best, float& bmax, int& bpos) {
    float m16[16]; int i16[16];
#pragma unroll
    for (int k = 0; k < 16; k++) {
        bool p = best[2*k] >= best[2*k+1];
        m16[k] = p ? best[2*k] : best[2*k+1];
        i16[k] = p ? 2*k : 2*k+1;
    }
    float m8[8]; int i8[8];
#pragma unroll
    for (int k = 0; k < 8; k++) {
        bool p = m16[2*k] >= m16[2*k+1];
        m8[k] = p ? m16[2*k] : m16[2*k+1];
        i8[k] = p ? i16[2*k] : i16[2*k+1];
    }
    float m4[4]; int i4[4];
#pragma unroll
    for (int k = 0; k < 4; k++) {
        bool p = m8[2*k] >= m8[2*k+1];
        m4[k] = p ? m8[2*k] : m8[2*k+1];
        i4[k] = p ? i8[2*k] : i8[2*k+1];
    }
    float m2[2]; int i2[2];
#pragma unroll
    for (int k = 0; k < 2; k++) {
        bool p = m4[2*k] >= m4[2*k+1];
        m2[k] = p ? m4[2*k] : m4[2*k+1];
        i2[k] = p ? i4[2*k] : i4[2*k+1];
    }
    bool p = m2[0] >= m2[1];
    bmax = p ? m2[0] : m2[1];
    bpos = p ? i2[0] : i2[1];
}

// ---------------- kernel 1: init + pixel + Y = x @ W1[:64] + W2t -----------
// 512 blocks x 256 threads.
__global__ void k_pre(const float* __restrict__ x, const float* __restrict__ pos,
                      const int* __restrict__ batch, const float* __restrict__ W1,
                      const float* __restrict__ W2, unsigned* __restrict__ out_u) {
    __shared__ float w1s[64 * C1];
    __shared__ float xs[64 * FF];
    int tid = threadIdx.x;
    int p0 = blockIdx.x * 64;

    // init output accumulator
    {
        uint4 v = make_uint4(ENC_NEG_INF, ENC_NEG_INF, ENC_NEG_INF, ENC_NEG_INF);
        uint4* o4 = (uint4*)out_u;
        int b4 = blockIdx.x * 1024 + tid;
        o4[b4] = v; o4[b4 + 256] = v; o4[b4 + 512] = v; o4[b4 + 768] = v;
    }
    // reset last-block counter
    if (blockIdx.x == 0 && tid == 0) g_cnt = 0;
    // W2 -> transposed slot-space tf32 (first 32 blocks)
    if (blockIdx.x < 32) {
        int i = blockIdx.x * 256 + tid;
        int n = i >> 7, sl = i & 127;
        g_W2t[n * C1 + sl] = __uint_as_float(f2tf32(W2[ch_of_slot(sl) * 64 + n]));
    }

    for (int i = tid; i < 64 * C1; i += 256) {
        int r = i >> 7, sl = i & 127;
        w1s[i] = W1[r * C1 + ch_of_slot(sl)];
    }
    for (int i = tid; i < 64 * FF; i += 256) xs[i] = x[p0 * FF + i];
    if (tid < 64) {
        int i = p0 + tid;
        float px = pos[2 * i], py = pos[2 * i + 1];
        int col = (int)(px * 32.0f); col = min(max(col, 0), 31);
        int row = (int)(py * 32.0f); row = min(max(row, 0), 31);
        g_pix[i] = batch[i] * (NB * NB) + row * 32 + col;
    }
    __syncthreads();

    int pg = tid >> 5;
    int c0 = (tid & 31) * 4;
    float acc[8][4];
#pragma unroll
    for (int p = 0; p < 8; p++)
#pragma unroll
        for (int c = 0; c < 4; c++) acc[p][c] = 0.f;

    for (int r = 0; r < 64; r++) {
        float4 w = *(const float4*)&w1s[r * C1 + c0];
#pragma unroll
        for (int p = 0; p < 8; p++) {
            float xv = xs[(pg * 8 + p) * FF + r];
            acc[p][0] = fmaf(xv, w.x, acc[p][0]);
            acc[p][1] = fmaf(xv, w.y, acc[p][1]);
            acc[p][2] = fmaf(xv, w.z, acc[p][2]);
            acc[p][3] = fmaf(xv, w.w, acc[p][3]);
        }
    }
#pragma unroll
    for (int p = 0; p < 8; p++) {
        int pt = p0 + pg * 8 + p;
        *(float4*)&g_Y[pt * C1 + c0] =
            make_float4(acc[p][0], acc[p][1], acc[p][2], acc[p][3]);
    }
}

// ---------------- kernel 2: binned radius K-NN -----------------------------
// 256 blocks x 128 threads; block owns 128 queries of one batch sample.
__global__ void k_nbr(const float* __restrict__ pos) {
    __shared__ float2 ps[PP];
    __shared__ float2 cpos[PP];      // positions in cell-sorted order
    __shared__ int cstart[GC * GC + 1];
    __shared__ int ccnt[GC * GC];
    __shared__ int cpts[PP];
    int tid = threadIdx.x;
    int b = blockIdx.x >> 3;
    int qoff = (blockIdx.x & 7) << 7;
    const float2* pb = (const float2*)pos + b * PP;
    for (int i = tid; i < PP; i += 128) ps[i] = pb[i];
    if (tid < GC * GC) ccnt[tid] = 0;
    __syncthreads();

    for (int j = tid; j < PP; j += 128) {
        int cx = min(max((int)(ps[j].x * GC), 0), GC - 1);
        int cy = min(max((int)(ps[j].y * GC), 0), GC - 1);
        atomicAdd(&ccnt[cy * GC + cx], 1);
    }
    __syncthreads();
    if (tid == 0) {
        int acc = 0;
        for (int i = 0; i < GC * GC; i++) { cstart[i] = acc; acc += ccnt[i]; }
        cstart[GC * GC] = acc;
    }
    __syncthreads();
    if (tid < GC * GC) ccnt[tid] = 0;
    __syncthreads();
    for (int j = tid; j < PP; j += 128) {
        int cx = min(max((int)(ps[j].x * GC), 0), GC - 1);
        int cy = min(max((int)(ps[j].y * GC), 0), GC - 1);
        int cid = cy * GC + cx;
        int p = cstart[cid] + atomicAdd(&ccnt[cid], 1);
        cpts[p] = j;
    }
    __syncthreads();
    // per-cell ascending-j sort (deterministic output order)
    if (tid < GC * GC) {
        int s0 = cstart[tid], s1 = cstart[tid + 1];
        for (int i = s0 + 1; i < s1; i++) {
            int v = cpts[i];
            int k = i - 1;
            while (k >= s0 && cpts[k] > v) { cpts[k + 1] = cpts[k]; k--; }
            cpts[k + 1] = v;
        }
    }
    __syncthreads();
    // gather positions into sorted order (kills the dependent-LDS chain)
    for (int p = tid; p < PP; p += 128) cpos[p] = ps[cpts[p]];
    __syncthreads();

    int ql = qoff + tid;
    int q = b * PP + ql;
    float qx = ps[ql].x, qy = ps[ql].y;
    const float R2 = 0.01f;
    const float INF = __int_as_float(0x7f800000);
    int pixq = g_pix[q];
    int cx0 = min(max((int)(qx * GC), 0), GC - 1);
    int cy0 = min(max((int)(qy * GC), 0), GC - 1);
    int cxlo = max(cx0 - 1, 0), cxhi = min(cx0 + 1, GC - 1);
    int cylo = max(cy0 - 1, 0), cyhi = min(cy0 + 1, GC - 1);

    float cd2[CAP];
    int   cj [CAP];
    int c = 0;
    for (int cy = cylo; cy <= cyhi; cy++) {
        int plo = cstart[cy * GC + cxlo];
        int phi = cstart[cy * GC + cxhi + 1];
#pragma unroll 2
        for (int p = plo; p < phi; p++) {
            float2 pj = cpos[p];
            float dx = __fsub_rn(qx, pj.x);
            float dy = __fsub_rn(qy, pj.y);
            float d2 = __fadd_rn(__fmul_rn(dx, dx), __fmul_rn(dy, dy));
            if (d2 <= R2) {
                if (c < CAP) { cd2[c] = d2; cj[c] = cpts[p]; }
                c++;
            }
        }
    }

    int kout = 0;
    if (c <= KK) {
        for (int i = 0; i < c; i++) {
            int s = b * PP + cj[i];
            if (s != pixq) g_nbr[q * KK + (kout++)] = s;
        }
    } else if (c <= CAP) {
        float best[32];
#pragma unroll
        for (int k = 0; k < 32; k++) best[k] = cd2[k];
        float bmax; int bpos;
        tree_max32(best, bmax, bpos);
        for (int i = 32; i < c; i++) {
            float d = cd2[i];
            if (d < bmax) {
#pragma unroll
                for (int k = 0; k < 32; k++) best[k] = (k == bpos) ? d : best[k];
                tree_max32(best, bmax, bpos);
            }
        }
        float t = bmax;
        int c1 = 0, nties = 0;
        for (int i = 0; i < c; i++) {
            c1    += (cd2[i] < t) ? 1 : 0;
            nties += (cd2[i] == t) ? 1 : 0;
        }
        int quota = KK - c1;
        if (quota >= nties) {
            for (int i = 0; i < c; i++) {
                if (cd2[i] <= t) {
                    int s = b * PP + cj[i];
                    if (s != pixq) g_nbr[q * KK + (kout++)] = s;
                }
            }
        } else {
            // NOTE: candidates are cell-sorted, not globally j-sorted; tie rank
            // must be computed by smallest-j among equal-d2 (matches top_k).
            for (int i = 0; i < c; i++) {
                bool take = (cd2[i] < t);
                if (!take && cd2[i] == t) {
                    int rank = 0;
                    for (int k2 = 0; k2 < c; k2++)
                        rank += (cd2[k2] == t && cj[k2] < cj[i]) ? 1 : 0;
                    take = (rank < quota);
                }
                if (take) {
                    int s = b * PP + cj[i];
                    if (s != pixq) g_nbr[q * KK + (kout++)] = s;
                }
            }
        }
        // outputs within radius arrive cell-sorted; edge SET matches reference.
        // (message order affects only our own BN partial-sum rounding)
    } else {
        // overflow fallback (never expected): full streaming scan over sample
        float best[32];
#pragma unroll
        for (int k = 0; k < 32; k++) best[k] = INF;
        float bmax = INF; int bpos = 0;
        for (int j = 0; j < PP; j++) {
            float dx = __fsub_rn(qx, ps[j].x);
            float dy = __fsub_rn(qy, ps[j].y);
            float d2 = __fadd_rn(__fmul_rn(dx, dx), __fmul_rn(dy, dy));
            if (d2 <= R2 && d2 < bmax) {
#pragma unroll
                for (int k = 0; k < 32; k++) best[k] = (k == bpos) ? d2 : best[k];
                tree_max32(best, bmax, bpos);
            }
        }
        float t = bmax;
        int c1 = 0;
        for (int j = 0; j < PP; j++) {
            float dx = __fsub_rn(qx, ps[j].x);
            float dy = __fsub_rn(qy, ps[j].y);
            float d2 = __fadd_rn(__fmul_rn(dx, dx), __fmul_rn(dy, dy));
            c1 += (d2 <= R2 && d2 < t) ? 1 : 0;
        }
        int quota = KK - c1;
        for (int j = 0; j < PP; j++) {
            float dx = __fsub_rn(qx, ps[j].x);
            float dy = __fsub_rn(qy, ps[j].y);
            float d2 = __fadd_rn(__fmul_rn(dx, dx), __fmul_rn(dy, dy));
            if (d2 > R2) continue;
            bool take = false;
            if (d2 < t) take = true;
            else if (d2 == t && quota > 0) { take = true; quota--; }
            if (take) {
                int s = b * PP + j;
                if (s != pixq) g_nbr[q * KK + (kout++)] = s;
            }
        }
    }
    for (; kout < KK; kout++) g_nbr[q * KK + kout] = -1;
}

// ---------------- kernel 3: BN stats + last-block reduce -> g_coef ---------
// 1024 blocks x 256 threads; block covers 32 queries (1056 messages).
__global__ void k_statsred(const float* __restrict__ pos, const float* __restrict__ W1,
                           const float* __restrict__ b1, const float* __restrict__ gamma1,
                           const float* __restrict__ beta1) {
    __shared__ int   es[1056];
    __shared__ float ex[1056];
    __shared__ float ey[1056];
    __shared__ float red[8 * C1];
    __shared__ int   redc[8];
    __shared__ int   lastflag;
    int tid = threadIdx.x;
    int q0 = blockIdx.x * 32;

    for (int idx = tid; idx < 1024; idx += 256) {
        int q = q0 + (idx >> 5);
        int s = g_nbr[q * KK + (idx & 31)];
        es[idx] = s;
        float rx = 0.f, ry = 0.f;
        if (s >= 0) {
            int d = g_pix[q];
            rx = pos[2 * s]     - pos[2 * d];
            ry = pos[2 * s + 1] - pos[2 * d + 1];
        }
        ex[idx] = rx; ey[idx] = ry;
    }
    if (tid < 32) { es[1024 + tid] = q0 + tid; ex[1024 + tid] = 0.f; ey[1024 + tid] = 0.f; }
    __syncthreads();

    int c4 = (tid & 31) * 4;
    int part = tid >> 5;
    float w64v[4], w65v[4], b1v[4];
#pragma unroll
    for (int u = 0; u < 4; u++) {
        int ch = ch_of_slot(c4 + u);
        w64v[u] = W1[64 * C1 + ch];
        w65v[u] = W1[65 * C1 + ch];
        b1v[u]  = b1[ch];
    }
    float sum[4] = {0.f, 0.f, 0.f, 0.f};
    float sq [4] = {0.f, 0.f, 0.f, 0.f};
    int cnt = 0;
    int m0 = part * 132;
#pragma unroll 4
    for (int m = m0; m < m0 + 132; m++) {
        int s = es[m];
        if (s < 0) continue;
        cnt++;
        float rx = ex[m], ry = ey[m];
        float4 y = *(const float4*)&g_Y[s * C1 + c4];
        float z0 = fmaf(rx, w64v[0], fmaf(ry, w65v[0], y.x + b1v[0]));
        float z1 = fmaf(rx, w64v[1], fmaf(ry, w65v[1], y.y + b1v[1]));
        float z2 = fmaf(rx, w64v[2], fmaf(ry, w65v[2], y.z + b1v[2]));
        float z3 = fmaf(rx, w64v[3], fmaf(ry, w65v[3], y.w + b1v[3]));
        sum[0] += z0; sum[1] += z1; sum[2] += z2; sum[3] += z3;
        sq[0] = fmaf(z0, z0, sq[0]); sq[1] = fmaf(z1, z1, sq[1]);
        sq[2] = fmaf(z2, z2, sq[2]); sq[3] = fmaf(z3, z3, sq[3]);
    }

    // in-block reduce: 8 partials -> 1 (fixed order, deterministic)
    *(float4*)&red[part * C1 + c4] = make_float4(sum[0], sum[1], sum[2], sum[3]);
    if ((tid & 31) == 0) redc[part] = cnt;
    __syncthreads();
    float ssum = 0.f;
    if (tid < C1) {
#pragma unroll
        for (int p = 0; p < 8; p++) ssum += red[p * C1 + tid];
    }
    __syncthreads();
    *(float4*)&red[part * C1 + c4] = make_float4(sq[0], sq[1], sq[2], sq[3]);
    __syncthreads();
    if (tid < C1) {
        float ssq = 0.f;
#pragma unroll
        for (int p = 0; p < 8; p++) ssq += red[p * C1 + tid];
        g_psum[blockIdx.x * C1 + tid] = ssum;
        g_psq [blockIdx.x * C1 + tid] = ssq;
    }
    if (tid == 0) {
        int t = 0;
#pragma unroll
        for (int p = 0; p < 8; p++) t += redc[p];
        g_pcnt[blockIdx.x] = t;
    }

    // last-block global reduce -> g_coef
    __threadfence();
    __syncthreads();
    if (tid == 0) lastflag = (atomicAdd(&g_cnt, 1) == NSLOT - 1) ? 1 : 0;
    __syncthreads();
    if (lastflag) {
        __threadfence();
        int c = tid >> 1, half = tid & 1;
        double s = 0.0, sqd = 0.0;
        long long tc = 0;
        int i0 = half * (NSLOT / 2);
        for (int i = i0; i < i0 + NSLOT / 2; i++) {
            s   += (double)__ldcg(&g_psum[i * C1 + c]);
            sqd += (double)__ldcg(&g_psq [i * C1 + c]);
            tc  += __ldcg(&g_pcnt[i]);
        }
        s   += __shfl_xor_sync(0xffffffffu, s, 1);
        sqd += __shfl_xor_sync(0xffffffffu, sqd, 1);
        tc  += __shfl_xor_sync(0xffffffffu, tc, 1);
        if (half == 0) {
            int ch = ch_of_slot(c);
            double mean = s / (double)tc;
            double var  = sqd / (double)tc - mean * mean;
            float A = gamma1[ch] / sqrtf((float)var + 1e-5f);
            g_coef[c]           = A;
            g_coef[C1 + c]      = W1[64 * C1 + ch] * A;
            g_coef[2 * C1 + c]  = W1[65 * C1 + ch] * A;
            g_coef[3 * C1 + c]  = beta1[ch] + (b1[ch] - (float)mean) * A;
        }
    }
}

// ---------------- kernel 4 (profiled): fused h -> tf32 mma -> max scatter --
// NBR_BLOCKS blocks: 4 queries x 32 edges. SELF_BLOCKS blocks: 128 self msgs.
__global__ void __launch_bounds__(256, 3)
k_main(const float* __restrict__ pos, const float* __restrict__ b2,
       unsigned* __restrict__ out_u) {
    extern __shared__ float sm[];
    float* hs  = sm;                        // [128 edges][HSH], 64 slots per half
    float* W2t = sm + 128 * HSH;            // [64 n][WS] tf32 bits
    float* ex2 = W2t + 64 * WS;
    float* ey2 = ex2 + 128;
    int*   es2 = (int*)(ey2 + 128);
    float* qmx = (float*)(es2 + 128);

    int tid = threadIdx.x;
    bool selfm = blockIdx.x >= NBR_BLOCKS;
    int q0 = blockIdx.x * 4;
    int s0 = (blockIdx.x - NBR_BLOCKS) * 128;
    const float NI = __int_as_float(0xff800000);

    for (int i = tid; i < 64 * C1; i += 256)
        W2t[(i >> 7) * WS + (i & 127)] = g_W2t[i];
    if (tid < 128) {
        if (!selfm) {
            int q = q0 + (tid >> 5);
            int s = g_nbr[q * KK + (tid & 31)];
            es2[tid] = s;
            float rx = 0.f, ry = 0.f;
            if (s >= 0) {
                int d = g_pix[q];
                rx = pos[2 * s]     - pos[2 * d];
                ry = pos[2 * s + 1] - pos[2 * d + 1];
            }
            ex2[tid] = rx; ey2[tid] = ry;
        } else {
            es2[tid] = s0 + tid;
            ex2[tid] = 0.f; ey2[tid] = 0.f;
        }
    }

    int lane = tid & 31, w = tid >> 5;
    int g = lane >> 2, t = lane & 3;
    int nh = w & 1, mh = w >> 1;
    int n0 = nh * 32;
    int e0 = mh * 32;

    float d[2][4][4];
#pragma unroll
    for (int a1 = 0; a1 < 2; a1++)
#pragma unroll
        for (int a2 = 0; a2 < 4; a2++)
#pragma unroll
            for (int a3 = 0; a3 < 4; a3++) d[a1][a2][a3] = 0.f;

    __syncthreads();

#pragma unroll
    for (int half = 0; half < 2; half++) {
        {
            int c4 = (tid & 15) * 4;
            int eg = tid >> 4;
            int sb = half * 64 + c4;
            float4 av = *(const float4*)&g_coef[sb];
            float4 xv = *(const float4*)&g_coef[C1 + sb];
            float4 yv = *(const float4*)&g_coef[2 * C1 + sb];
            float4 bv = *(const float4*)&g_coef[3 * C1 + sb];
#pragma unroll
            for (int e = 0; e < 8; e++) {
                int ee = eg * 8 + e;
                int s = es2[ee];
                float4 h = make_float4(0.f, 0.f, 0.f, 0.f);
                if (s >= 0) {
                    float4 y = *(const float4*)&g_Y[s * C1 + sb];
                    float rx = ex2[ee], ry = ey2[ee];
                    h.x = fmaxf(fmaf(y.x, av.x, fmaf(rx, xv.x, fmaf(ry, yv.x, bv.x))), 0.f);
                    h.y = fmaxf(fmaf(y.y, av.y, fmaf(rx, xv.y, fmaf(ry, yv.y, bv.y))), 0.f);
                    h.z = fmaxf(fmaf(y.z, av.z, fmaf(rx, xv.z, fmaf(ry, yv.z, bv.z))), 0.f);
                    h.w = fmaxf(fmaf(y.w, av.w, fmaf(rx, xv.w, fmaf(ry, yv.w, bv.w))), 0.f);
                }
                float4 ht;
                ht.x = __uint_as_float(f2tf32(h.x));
                ht.y = __uint_as_float(f2tf32(h.y));
                ht.z = __uint_as_float(f2tf32(h.z));
                ht.w = __uint_as_float(f2tf32(h.w));
                *(float4*)&hs[ee * HSH + c4] = ht;
            }
        }
        __syncthreads();

#pragma unroll
        for (int ks = 0; ks < 8; ks++) {
            int kg = half * 64 + ks * 8;
            int kh = ks * 8;
            unsigned bb[4][2];
#pragma unroll
            for (int nt = 0; nt < 4; nt++) {
                float2 bv = *(const float2*)&W2t[(n0 + nt * 8 + g) * WS + kg + 2 * t];
                bb[nt][0] = __float_as_uint(bv.x);
                bb[nt][1] = __float_as_uint(bv.y);
            }
#pragma unroll
            for (int mt = 0; mt < 2; mt++) {
                const float* hp = hs + (e0 + mt * 16 + g) * HSH + kh + 2 * t;
                float2 alo = *(const float2*)hp;
                float2 ahi = *(const float2*)(hp + 8 * HSH);
                unsigned a0 = __float_as_uint(alo.x);
                unsigned a2 = __float_as_uint(alo.y);
                unsigned a1 = __float_as_uint(ahi.x);
                unsigned a3 = __float_as_uint(ahi.y);
#pragma unroll
                for (int nt = 0; nt < 4; nt++) {
                    asm volatile(
                        "mma.sync.aligned.m16n8k8.row.col.f32.tf32.tf32.f32 "
                        "{%0,%1,%2,%3}, {%4,%5,%6,%7}, {%8,%9}, {%0,%1,%2,%3};"
                        : "+f"(d[mt][nt][0]), "+f"(d[mt][nt][1]),
                          "+f"(d[mt][nt][2]), "+f"(d[mt][nt][3])
                        : "r"(a0), "r"(a1), "r"(a2), "r"(a3),
                          "r"(bb[nt][0]), "r"(bb[nt][1]));
                }
            }
        }
        __syncthreads();
    }

    if (!selfm) {
        float rm[4][2];
#pragma unroll
        for (int nt = 0; nt < 4; nt++) { rm[nt][0] = NI; rm[nt][1] = NI; }
#pragma unroll
        for (int mt = 0; mt < 2; mt++) {
            bool vlo = es2[e0 + mt * 16 + g] >= 0;
            bool vhi = es2[e0 + mt * 16 + 8 + g] >= 0;
#pragma unroll
            for (int nt = 0; nt < 4; nt++) {
                float x0 = vlo ? d[mt][nt][0] : NI;
                float x1 = vlo ? d[mt][nt][1] : NI;
                float x2 = vhi ? d[mt][nt][2] : NI;
                float x3 = vhi ? d[mt][nt][3] : NI;
                rm[nt][0] = fmaxf(rm[nt][0], fmaxf(x0, x2));
                rm[nt][1] = fmaxf(rm[nt][1], fmaxf(x1, x3));
            }
        }
#pragma unroll
        for (int nt = 0; nt < 4; nt++)
#pragma unroll
            for (int j = 0; j < 2; j++) {
                float v = rm[nt][j];
                v = fmaxf(v, __shfl_xor_sync(0xffffffffu, v, 4));
                v = fmaxf(v, __shfl_xor_sync(0xffffffffu, v, 8));
                v = fmaxf(v, __shfl_xor_sync(0xffffffffu, v, 16));
                rm[nt][j] = v;
            }
        if (lane < 4) {
#pragma unroll
            for (int nt = 0; nt < 4; nt++) {
                qmx[mh * 64 + n0 + nt * 8 + 2 * t]     = rm[nt][0];
                qmx[mh * 64 + n0 + nt * 8 + 2 * t + 1] = rm[nt][1];
            }
        }
        __syncthreads();
        float v = qmx[tid];
        if (__float_as_uint(v) != 0xff800000u) {
            int col = tid & 63, qloc = tid >> 6;
            int q = q0 + qloc;
            int P = g_pix[q];
            atomicMax(&out_u[(P >> 10) * (FF * PP) + col * PP + (P & 1023)],
                      encf(v + b2[col]));
        }
    } else {
        // self mode: every accumulator element targets its own node
#pragma unroll
        for (int mt = 0; mt < 2; mt++) {
            int r0 = s0 + e0 + mt * 16 + g;
            int r1 = r0 + 8;
            unsigned ob0 = (unsigned)((r0 >> 10) * (FF * PP) + (r0 & 1023));
            unsigned ob1 = (unsigned)((r1 >> 10) * (FF * PP) + (r1 & 1023));
#pragma unroll
            for (int nt = 0; nt < 4; nt++) {
                int col0 = n0 + nt * 8 + 2 * t;
                float bv0 = b2[col0], bv1 = b2[col0 + 1];
                atomicMax(&out_u[ob0 + col0 * PP],       encf(d[mt][nt][0] + bv0));
                atomicMax(&out_u[ob0 + (col0 + 1) * PP], encf(d[mt][nt][1] + bv1));
                atomicMax(&out_u[ob1 + col0 * PP],       encf(d[mt][nt][2] + bv0));
                atomicMax(&out_u[ob1 + (col0 + 1) * PP], encf(d[mt][nt][3] + bv1));
            }
        }
    }
}

// ---------------- kernel 5: decode in place ----------------
__global__ void k_decode(unsigned* __restrict__ out_u) {
    int i = blockIdx.x * 256 + threadIdx.x;
    if (i < NPTS * FF) {
        unsigned u = out_u[i];
        ((float*)out_u)[i] = decf(u);
    }
}

// ---------------- launch ----------------
extern "C" void kernel_launch(void* const* d_in, const int* in_sizes, int n_in,
                              void* d_out, int out_size) {
    const float* x      = (const float*)d_in[0];
    const float* pos    = (const float*)d_in[1];
    const int*   batch  = (const int*)  d_in[2];
    const float* W1     = (const float*)d_in[3];
    const float* b1     = (const float*)d_in[4];
    const float* gamma1 = (const float*)d_in[5];
    const float* beta1  = (const float*)d_in[6];
    const float* W2     = (const float*)d_in[7];
    const float* b2     = (const float*)d_in[8];
    unsigned* out_u = (unsigned*)d_out;

    cudaFuncSetAttribute(k_main, cudaFuncAttributeMaxDynamicSharedMemorySize, SMEM_MAIN_BYTES);

    k_pre     <<<NPTS / 64, 256>>>(x, pos, batch, W1, W2, out_u);        // 1
    k_nbr     <<<NPTS / 128, 128>>>(pos);                                 // 2
    k_statsred<<<NSLOT, 256>>>(pos, W1, b1, gamma1, beta1);               // 3
    k_main    <<<NBR_BLOCKS + SELF_BLOCKS, 256, SMEM_MAIN_BYTES>>>(pos, b2, out_u); // 4 <- profiled
    k_decode  <<<(NPTS * FF + 255) / 256, 256>>>(out_u);                  // 5
}